// round 3
// baseline (speedup 1.0000x reference)
#include <cuda_runtime.h>
#include <cuda_bf16.h>

// Problem constants
#define BB 8
#define TT 1024
#define EE 128
#define HH 8
#define DHD 16
#define E3 384

// ---------------------------------------------------------------------------
// Scratch (allocation-free: __device__ globals)
// q/k/v packed as [B,H,T,32]: cols 0..15 = re, 16..31 = im.
// Q is pre-scaled by DH^-0.5 = 0.25 so Re(q.conj(k)) dot over 32 gives the
// already-scaled real score.
// ---------------------------------------------------------------------------
__device__ float g_q[BB * HH * TT * 32];
__device__ float g_k[BB * HH * TT * 32];
__device__ float g_v[BB * HH * TT * 32];
__device__ float g_or[BB * TT * EE];
__device__ float g_oi[BB * TT * EE];
__device__ float g_W2r[EE * EE];
__device__ float g_W2i[EE * EE];
__device__ float g_b2r[EE];
__device__ float g_b2i[EE];

// ---------------------------------------------------------------------------
// Kernel 0: fold the two output linears into one.
//   W2 = wt @ wout   (complex [E,E]),  b2 = wt @ bout + bt
// ---------------------------------------------------------------------------
__global__ void combine_kernel(const float* __restrict__ wtr, const float* __restrict__ wti,
                               const float* __restrict__ wor, const float* __restrict__ woi,
                               const float* __restrict__ bor, const float* __restrict__ boi,
                               const float* __restrict__ btr, const float* __restrict__ bti)
{
    int j = blockIdx.x;      // 0..127
    int e = threadIdx.x;     // 0..127
    float accr = 0.f, acci = 0.f;
    for (int m = 0; m < EE; ++m) {
        float a = wtr[j * EE + m], c = wti[j * EE + m];
        float u = wor[m * EE + e], v = woi[m * EE + e];
        accr += a * u - c * v;
        acci += a * v + c * u;
    }
    g_W2r[j * EE + e] = accr;
    g_W2i[j * EE + e] = acci;
    if (e == 0) {
        float r = btr[j], im = bti[j];
        for (int m = 0; m < EE; ++m) {
            r  += wtr[j * EE + m] * bor[m] - wti[j * EE + m] * boi[m];
            im += wtr[j * EE + m] * boi[m] + wti[j * EE + m] * bor[m];
        }
        g_b2r[j] = r;
        g_b2i[j] = im;
    }
}

// ---------------------------------------------------------------------------
// Kernel 1: complex QKV projection.
// A = xs [M=8192, K=128] with xs[b*T+t, e] = x[b, e, t] (x is [B,E,T] flat).
// Bmat = win [384, 128].  qkv[m, j] = sum_e xs[m,e] * win[j,e]  (complex)
// Tiled 64 tokens x 64 outputs, 256 threads, 4x4 per-thread complex tile.
// Epilogue scatters directly into packed q/k/v [B,H,T,32] (+bias, q*0.25).
// ---------------------------------------------------------------------------
__global__ __launch_bounds__(256)
void qkv_kernel(const float* __restrict__ xr, const float* __restrict__ xi,
                const float* __restrict__ wr, const float* __restrict__ wi,
                const float* __restrict__ br, const float* __restrict__ bi)
{
    __shared__ float sxr[16][68], sxi[16][68], swr[16][68], swi[16][68];

    const int m0 = blockIdx.x * 64;      // token tile base
    const int n0 = blockIdx.y * 64;      // output tile base (of 384)
    const int b  = m0 >> 10;
    const int t0 = m0 & (TT - 1);
    const int tid = threadIdx.x;
    const int tx = tid & 15;             // output group (4 outputs)
    const int ty = tid >> 4;             // token group  (4 tokens)

    float ar[4][4], ai[4][4];
#pragma unroll
    for (int i = 0; i < 4; ++i)
#pragma unroll
        for (int j = 0; j < 4; ++j) { ar[i][j] = 0.f; ai[i][j] = 0.f; }

    const float* xrb = xr + (long)b * EE * TT;
    const float* xib = xi + (long)b * EE * TT;

    for (int k0 = 0; k0 < EE; k0 += 16) {
        // x tile: [16 k][64 tokens], coalesced along t
#pragma unroll
        for (int u = 0; u < 4; ++u) {
            int li = u * 256 + tid;      // 0..1023
            int kk = li >> 6, mm = li & 63;
            sxr[kk][mm] = xrb[(k0 + kk) * TT + t0 + mm];
            sxi[kk][mm] = xib[(k0 + kk) * TT + t0 + mm];
        }
        // w tile transposed to [16 k][64 outputs]
        {
            int r = tid >> 2;            // output row 0..63
            int q = tid & 3;             // float4 index in row
            float4 a4 = *(const float4*)&wr[(n0 + r) * EE + k0 + q * 4];
            float4 b4 = *(const float4*)&wi[(n0 + r) * EE + k0 + q * 4];
            swr[q * 4 + 0][r] = a4.x; swr[q * 4 + 1][r] = a4.y;
            swr[q * 4 + 2][r] = a4.z; swr[q * 4 + 3][r] = a4.w;
            swi[q * 4 + 0][r] = b4.x; swi[q * 4 + 1][r] = b4.y;
            swi[q * 4 + 2][r] = b4.z; swi[q * 4 + 3][r] = b4.w;
        }
        __syncthreads();
#pragma unroll
        for (int kk = 0; kk < 16; ++kk) {
            float xr0[4], xi0[4], wr0[4], wi0[4];
#pragma unroll
            for (int u = 0; u < 4; ++u) {
                xr0[u] = sxr[kk][ty * 4 + u];
                xi0[u] = sxi[kk][ty * 4 + u];
                wr0[u] = swr[kk][tx * 4 + u];
                wi0[u] = swi[kk][tx * 4 + u];
            }
#pragma unroll
            for (int i = 0; i < 4; ++i)
#pragma unroll
                for (int j = 0; j < 4; ++j) {
                    ar[i][j] += xr0[i] * wr0[j] - xi0[i] * wi0[j];
                    ai[i][j] += xr0[i] * wi0[j] + xi0[i] * wr0[j];
                }
        }
        __syncthreads();
    }

    // Epilogue: bias + scatter to packed q/k/v
#pragma unroll
    for (int j = 0; j < 4; ++j) {
        int n = n0 + tx * 4 + j;         // 0..383
        float bre = br[n], bim = bi[n];
        int sec  = n >> 7;               // 0=q 1=k 2=v
        int rloc = n & 127;
        int h = rloc >> 4, d = rloc & 15;
        float* dst = (sec == 0) ? g_q : ((sec == 1) ? g_k : g_v);
        float scl = (sec == 0) ? 0.25f : 1.0f;
#pragma unroll
        for (int i = 0; i < 4; ++i) {
            int t = t0 + ty * 4 + i;
            int base = (((b * HH + h) * TT) + t) * 32;
            dst[base + d]      = (ar[i][j] + bre) * scl;
            dst[base + 16 + d] = (ai[i][j] + bim) * scl;
        }
    }
}

// ---------------------------------------------------------------------------
// Kernel 2: flash attention, real scores with d=32 (re||im), real softmax,
// complex V packed as 32. One query per thread, 128 queries per block,
// 64-key tiles in smem (K/V reads are warp-uniform broadcasts -> FMA-bound).
// grid = (T/128, H, B)
// ---------------------------------------------------------------------------
__global__ __launch_bounds__(128)
void attn_kernel()
{
    __shared__ float4 sk[64][8];   // 64 keys x 32 floats
    __shared__ float4 sv[64][8];

    const int b = blockIdx.z, h = blockIdx.y;
    const int bh = b * HH + h;
    const int qi = blockIdx.x * 128 + threadIdx.x;

    const float4* qp = (const float4*)(g_q + ((bh * TT) + qi) * 32);
    float4 q4[8];
#pragma unroll
    for (int u = 0; u < 8; ++u) q4[u] = qp[u];

    float4 o4[8];
#pragma unroll
    for (int u = 0; u < 8; ++u) o4[u] = make_float4(0.f, 0.f, 0.f, 0.f);
    float m = -1e30f, l = 0.f;

    const float4* kg = (const float4*)(g_k + (long)bh * TT * 32);
    const float4* vg = (const float4*)(g_v + (long)bh * TT * 32);

    for (int j0 = 0; j0 < TT; j0 += 64) {
        __syncthreads();
#pragma unroll
        for (int u = 0; u < 4; ++u) {
            int li = u * 128 + threadIdx.x;     // 0..511 float4s per array
            sk[li >> 3][li & 7] = kg[j0 * 8 + li];
            sv[li >> 3][li & 7] = vg[j0 * 8 + li];
        }
        __syncthreads();

#pragma unroll 1
        for (int jj0 = 0; jj0 < 64; jj0 += 8) {
            float s[8];
#pragma unroll
            for (int jj = 0; jj < 8; ++jj) {
                const float4* kp = sk[jj0 + jj];
                float acc = 0.f;
#pragma unroll
                for (int u = 0; u < 8; ++u) {
                    float4 kv = kp[u];
                    acc += q4[u].x * kv.x + q4[u].y * kv.y
                         + q4[u].z * kv.z + q4[u].w * kv.w;
                }
                s[jj] = acc;
            }
            float mt = s[0];
#pragma unroll
            for (int jj = 1; jj < 8; ++jj) mt = fmaxf(mt, s[jj]);
            float mnew = fmaxf(m, mt);
            float corr = __expf(m - mnew);
            float p[8], ps = 0.f;
#pragma unroll
            for (int jj = 0; jj < 8; ++jj) { p[jj] = __expf(s[jj] - mnew); ps += p[jj]; }
            l = l * corr + ps;
            m = mnew;
#pragma unroll
            for (int u = 0; u < 8; ++u) {
                float4 a = o4[u];
                a.x *= corr; a.y *= corr; a.z *= corr; a.w *= corr;
#pragma unroll
                for (int jj = 0; jj < 8; ++jj) {
                    float4 vv = sv[jj0 + jj][u];
                    float pw = p[jj];
                    a.x += pw * vv.x; a.y += pw * vv.y;
                    a.z += pw * vv.z; a.w += pw * vv.w;
                }
                o4[u] = a;
            }
        }
    }

    float inv = 1.f / l;
    float* pr = g_or + ((b * TT + qi) * EE) + h * DHD;
    float* pi = g_oi + ((b * TT + qi) * EE) + h * DHD;
#pragma unroll
    for (int u = 0; u < 4; ++u) {
        float4 a = o4[u];
        a.x *= inv; a.y *= inv; a.z *= inv; a.w *= inv;
        *(float4*)(pr + u * 4) = a;
        float4 c = o4[u + 4];
        c.x *= inv; c.y *= inv; c.z *= inv; c.w *= inv;
        *(float4*)(pi + u * 4) = c;
    }
}

// ---------------------------------------------------------------------------
// Kernel 3: y = o @ W2^T + b2 (complex), stored transposed to [2,B,E,T].
// Thread mapping puts consecutive tokens in consecutive lanes -> coalesced
// float4 stores along T for each output row.
// ---------------------------------------------------------------------------
__global__ __launch_bounds__(256)
void out_kernel(float* __restrict__ out)
{
    __shared__ float sxr[16][68], sxi[16][68], swr[16][68], swi[16][68];

    const int m0 = blockIdx.x * 64;
    const int n0 = blockIdx.y * 64;
    const int b  = m0 >> 10;
    const int t0 = m0 & (TT - 1);
    const int tid = threadIdx.x;
    const int tx = tid & 15;       // token group (coalesced stores)
    const int ty = tid >> 4;       // output group

    float ar[4][4], ai[4][4];      // [token][out]
#pragma unroll
    for (int i = 0; i < 4; ++i)
#pragma unroll
        for (int j = 0; j < 4; ++j) { ar[i][j] = 0.f; ai[i][j] = 0.f; }

    for (int k0 = 0; k0 < EE; k0 += 16) {
        {
            int r = tid >> 2;   // token row
            int q = tid & 3;
            float4 a4 = *(const float4*)&g_or[(m0 + r) * EE + k0 + q * 4];
            float4 b4 = *(const float4*)&g_oi[(m0 + r) * EE + k0 + q * 4];
            sxr[q * 4 + 0][r] = a4.x; sxr[q * 4 + 1][r] = a4.y;
            sxr[q * 4 + 2][r] = a4.z; sxr[q * 4 + 3][r] = a4.w;
            sxi[q * 4 + 0][r] = b4.x; sxi[q * 4 + 1][r] = b4.y;
            sxi[q * 4 + 2][r] = b4.z; sxi[q * 4 + 3][r] = b4.w;
        }
        {
            int r = tid >> 2;   // output row
            int q = tid & 3;
            float4 a4 = *(const float4*)&g_W2r[(n0 + r) * EE + k0 + q * 4];
            float4 b4 = *(const float4*)&g_W2i[(n0 + r) * EE + k0 + q * 4];
            swr[q * 4 + 0][r] = a4.x; swr[q * 4 + 1][r] = a4.y;
            swr[q * 4 + 2][r] = a4.z; swr[q * 4 + 3][r] = a4.w;
            swi[q * 4 + 0][r] = b4.x; swi[q * 4 + 1][r] = b4.y;
            swi[q * 4 + 2][r] = b4.z; swi[q * 4 + 3][r] = b4.w;
        }
        __syncthreads();
#pragma unroll
        for (int kk = 0; kk < 16; ++kk) {
            float xr0[4], xi0[4], wr0[4], wi0[4];
#pragma unroll
            for (int u = 0; u < 4; ++u) {
                xr0[u] = sxr[kk][tx * 4 + u];   // per-lane tokens
                xi0[u] = sxi[kk][tx * 4 + u];
                wr0[u] = swr[kk][ty * 4 + u];   // broadcast outputs
                wi0[u] = swi[kk][ty * 4 + u];
            }
#pragma unroll
            for (int i = 0; i < 4; ++i)
#pragma unroll
                for (int j = 0; j < 4; ++j) {
                    ar[i][j] += xr0[i] * wr0[j] - xi0[i] * wi0[j];
                    ai[i][j] += xr0[i] * wi0[j] + xi0[i] * wr0[j];
                }
        }
        __syncthreads();
    }

    const int IM_OFF = BB * EE * TT;   // offset of imag component block
#pragma unroll
    for (int j = 0; j < 4; ++j) {
        int n = n0 + ty * 4 + j;
        float brr = g_b2r[n], bii = g_b2i[n];
        float4 vr = make_float4(ar[0][j] + brr, ar[1][j] + brr,
                                ar[2][j] + brr, ar[3][j] + brr);
        float4 vi = make_float4(ai[0][j] + bii, ai[1][j] + bii,
                                ai[2][j] + bii, ai[3][j] + bii);
        int t = t0 + tx * 4;
        float* pr = out + ((b * EE + n) * TT) + t;
        *(float4*)pr = vr;
        *(float4*)(pr + IM_OFF) = vi;
    }
}

// ---------------------------------------------------------------------------
extern "C" void kernel_launch(void* const* d_in, const int* in_sizes, int n_in,
                              void* d_out, int out_size)
{
    const float* xr  = (const float*)d_in[0];
    const float* xi  = (const float*)d_in[1];
    const float* wir = (const float*)d_in[2];
    const float* wii = (const float*)d_in[3];
    const float* bir = (const float*)d_in[4];
    const float* bii = (const float*)d_in[5];
    const float* wor = (const float*)d_in[6];
    const float* woi = (const float*)d_in[7];
    const float* bor = (const float*)d_in[8];
    const float* boi = (const float*)d_in[9];
    const float* wtr = (const float*)d_in[10];
    const float* wti = (const float*)d_in[11];
    const float* btr = (const float*)d_in[12];
    const float* bti = (const float*)d_in[13];

    combine_kernel<<<EE, EE>>>(wtr, wti, wor, woi, bor, boi, btr, bti);
    qkv_kernel<<<dim3((BB * TT) / 64, E3 / 64), 256>>>(xr, xi, wir, wii, bir, bii);
    attn_kernel<<<dim3(TT / 128, HH, BB), 128>>>();
    out_kernel<<<dim3((BB * TT) / 64, EE / 64), 256>>>((float*)d_out);
}

// round 5
// speedup vs baseline: 1.9112x; 1.9112x over previous
#include <cuda_runtime.h>
#include <cuda_bf16.h>

// Problem constants
#define BB 8
#define TT 1024
#define EE 128
#define HH 8
#define DHD 16
#define E3 384

// ---------------------------------------------------------------------------
// Scratch (allocation-free: __device__ globals)
//
// Q/K/V are stored PRE-SWIZZLED into mma.sync.m16n8k8 tf32 fragment layout,
// per (b,h) slice, logical [T, 32] where cols 0..15 = re, 16..31 = im.
//   Q: [bh][qb=T/16][ks=4][lane=32][reg=4]   (A fragments, rows=queries)
//   K: [bh][kb=T/8 ][ks=4][lane=32][reg=2]   (B fragments for S=Q K^T)
//   V: [bh][ksb=T/8][nb=4][lane=32][reg=2]   (B fragments for O=P V)
// Values are tf32-rounded (cvt.rna) floats. Q also carries 0.25*log2(e) so
// softmax can use raw ex2.
// ---------------------------------------------------------------------------
__device__ float g_q[BB * HH * TT * 32];
__device__ float g_k[BB * HH * TT * 32];
__device__ float g_v[BB * HH * TT * 32];
__device__ float g_or[BB * TT * EE];
__device__ float g_oi[BB * TT * EE];
__device__ float g_W2r[EE * EE];
__device__ float g_W2i[EE * EE];
__device__ float g_b2r[EE];
__device__ float g_b2i[EE];

__device__ __forceinline__ float ex2f(float x) {
    float r; asm("ex2.approx.ftz.f32 %0, %1;" : "=f"(r) : "f"(x)); return r;
}
__device__ __forceinline__ unsigned int totf(float x) {
    unsigned int u; asm("cvt.rna.tf32.f32 %0, %1;" : "=r"(u) : "f"(x)); return u;
}
__device__ __forceinline__ void mma8(float* d, const unsigned int* a,
                                     unsigned int b0, unsigned int b1) {
    asm volatile(
        "mma.sync.aligned.m16n8k8.row.col.f32.tf32.tf32.f32 "
        "{%0,%1,%2,%3},{%4,%5,%6,%7},{%8,%9},{%0,%1,%2,%3};"
        : "+f"(d[0]), "+f"(d[1]), "+f"(d[2]), "+f"(d[3])
        : "r"(a[0]), "r"(a[1]), "r"(a[2]), "r"(a[3]), "r"(b0), "r"(b1));
}

// ---------------------------------------------------------------------------
// Kernel 0: fold the two output linears into one.
//   W2 = wt @ wout   (complex [E,E]),  b2 = wt @ bout + bt
// ---------------------------------------------------------------------------
__global__ void combine_kernel(const float* __restrict__ wtr, const float* __restrict__ wti,
                               const float* __restrict__ wor, const float* __restrict__ woi,
                               const float* __restrict__ bor, const float* __restrict__ boi,
                               const float* __restrict__ btr, const float* __restrict__ bti)
{
    int j = blockIdx.x;      // 0..127
    int e = threadIdx.x;     // 0..127
    float accr = 0.f, acci = 0.f;
    for (int m = 0; m < EE; ++m) {
        float a = wtr[j * EE + m], c = wti[j * EE + m];
        float u = wor[m * EE + e], v = woi[m * EE + e];
        accr += a * u - c * v;
        acci += a * v + c * u;
    }
    g_W2r[j * EE + e] = accr;
    g_W2i[j * EE + e] = acci;
    if (e == 0) {
        float r = btr[j], im = bti[j];
        for (int m = 0; m < EE; ++m) {
            r  += wtr[j * EE + m] * bor[m] - wti[j * EE + m] * boi[m];
            im += wtr[j * EE + m] * boi[m] + wti[j * EE + m] * bor[m];
        }
        g_b2r[j] = r;
        g_b2i[j] = im;
    }
}

// ---------------------------------------------------------------------------
// Kernel 1: complex QKV projection (fp32 GEMM core unchanged).
// Epilogue scatters into mma fragment layouts (+bias, Q scaled, tf32-rounded).
// ---------------------------------------------------------------------------
__global__ __launch_bounds__(256)
void qkv_kernel(const float* __restrict__ xr, const float* __restrict__ xi,
                const float* __restrict__ wr, const float* __restrict__ wi,
                const float* __restrict__ br, const float* __restrict__ bi)
{
    __shared__ float sxr[16][68], sxi[16][68], swr[16][68], swi[16][68];

    const int m0 = blockIdx.x * 64;      // token tile base
    const int n0 = blockIdx.y * 64;      // output tile base (of 384)
    const int b  = m0 >> 10;
    const int t0 = m0 & (TT - 1);
    const int tid = threadIdx.x;
    const int tx = tid & 15;             // output group (4 outputs)
    const int ty = tid >> 4;             // token group  (4 tokens)

    float ar[4][4], ai[4][4];
#pragma unroll
    for (int i = 0; i < 4; ++i)
#pragma unroll
        for (int j = 0; j < 4; ++j) { ar[i][j] = 0.f; ai[i][j] = 0.f; }

    const float* xrb = xr + (long)b * EE * TT;
    const float* xib = xi + (long)b * EE * TT;

    for (int k0 = 0; k0 < EE; k0 += 16) {
#pragma unroll
        for (int u = 0; u < 4; ++u) {
            int li = u * 256 + tid;
            int kk = li >> 6, mm = li & 63;
            sxr[kk][mm] = xrb[(k0 + kk) * TT + t0 + mm];
            sxi[kk][mm] = xib[(k0 + kk) * TT + t0 + mm];
        }
        {
            int r = tid >> 2;
            int q = tid & 3;
            float4 a4 = *(const float4*)&wr[(n0 + r) * EE + k0 + q * 4];
            float4 b4 = *(const float4*)&wi[(n0 + r) * EE + k0 + q * 4];
            swr[q * 4 + 0][r] = a4.x; swr[q * 4 + 1][r] = a4.y;
            swr[q * 4 + 2][r] = a4.z; swr[q * 4 + 3][r] = a4.w;
            swi[q * 4 + 0][r] = b4.x; swi[q * 4 + 1][r] = b4.y;
            swi[q * 4 + 2][r] = b4.z; swi[q * 4 + 3][r] = b4.w;
        }
        __syncthreads();
#pragma unroll
        for (int kk = 0; kk < 16; ++kk) {
            float xr0[4], xi0[4], wr0[4], wi0[4];
#pragma unroll
            for (int u = 0; u < 4; ++u) {
                xr0[u] = sxr[kk][ty * 4 + u];
                xi0[u] = sxi[kk][ty * 4 + u];
                wr0[u] = swr[kk][tx * 4 + u];
                wi0[u] = swi[kk][tx * 4 + u];
            }
#pragma unroll
            for (int i = 0; i < 4; ++i)
#pragma unroll
                for (int j = 0; j < 4; ++j) {
                    ar[i][j] += xr0[i] * wr0[j] - xi0[i] * wi0[j];
                    ai[i][j] += xr0[i] * wi0[j] + xi0[i] * wr0[j];
                }
        }
        __syncthreads();
    }

    // Epilogue: bias + scatter to fragment-layout q/k/v (tf32-rounded)
    const float QS = 0.25f * 1.44269504088896f;   // DH^-0.5 * log2(e)
#pragma unroll
    for (int j = 0; j < 4; ++j) {
        int n = n0 + tx * 4 + j;         // 0..383
        float bre = br[n], bim = bi[n];
        int sec  = n >> 7;               // 0=q 1=k 2=v
        int rloc = n & 127;
        int h = rloc >> 4, d = rloc & 15;
#pragma unroll
        for (int i = 0; i < 4; ++i) {
            int tloc = t0 + ty * 4 + i;
            int bh = b * HH + h;
            float vr = ar[i][j] + bre;
            float vi = ai[i][j] + bim;
            if (sec == 0) {
                vr *= QS; vi *= QS;
                int qb = tloc >> 4, r = tloc & 15;
                int gq = r & 7, hi = r >> 3;
#pragma unroll
                for (int p = 0; p < 2; ++p) {
                    int c = d + p * 16;
                    float v = p ? vi : vr;
                    int ks = c >> 3, tl = c & 7;
                    int reg = ((tl & 4) >> 1) + hi;
                    int lane = gq * 4 + (tl & 3);
                    g_q[(((bh * 64 + qb) * 4 + ks) * 128) + lane * 4 + reg] =
                        __uint_as_float(totf(v));
                }
            } else if (sec == 1) {
                int kb = tloc >> 3, gk = tloc & 7;
#pragma unroll
                for (int p = 0; p < 2; ++p) {
                    int c = d + p * 16;
                    float v = p ? vi : vr;
                    int ks = c >> 3, tl = c & 7;
                    int jj = (tl >> 2) & 1;
                    int lane = gk * 4 + (tl & 3);
                    g_k[(((bh * 128 + kb) * 4 + ks) * 64) + lane * 2 + jj] =
                        __uint_as_float(totf(v));
                }
            } else {
                int ksb = tloc >> 3, r = tloc & 7;
                int jj = (r >> 2) & 1, tl = r & 3;
#pragma unroll
                for (int p = 0; p < 2; ++p) {
                    int c = d + p * 16;
                    float v = p ? vi : vr;
                    int nb = c >> 3, gc = c & 7;
                    int lane = gc * 4 + tl;
                    g_v[(((bh * 128 + ksb) * 4 + nb) * 64) + lane * 2 + jj] =
                        __uint_as_float(totf(v));
                }
            }
        }
    }
}

// ---------------------------------------------------------------------------
// Kernel 2: flash attention on tensor cores (tf32 mma.sync m16n8k8).
// Real scores d=32 (re||im), online softmax (base-2), complex V packed 32.
// 4 warps/CTA, each warp owns 16 queries; key tiles of 64 in smem.
// grid = (T/64, H, B), block = 128.
// ---------------------------------------------------------------------------
__global__ __launch_bounds__(128)
void attn_kernel()
{
    __shared__ float sK[2048];    // 8 key-blocks x 4 ks x 32 lanes x 2
    __shared__ float sV[2048];    // 8 key-steps x 4 nb x 32 lanes x 2

    const int b = blockIdx.z, h = blockIdx.y;
    const int bh = b * HH + h;
    const int tid = threadIdx.x;
    const int warp = tid >> 5, lane = tid & 31;
    const int g = lane >> 2, tq = lane & 3;
    const int qb = blockIdx.x * 4 + warp;      // 16-query block within bh

    // Q fragments (loaded once)
    unsigned int qA[4][4];
#pragma unroll
    for (int ks = 0; ks < 4; ++ks) {
        uint4 v = ((const uint4*)g_q)[((bh * 64 + qb) * 4 + ks) * 32 + lane];
        qA[ks][0] = v.x; qA[ks][1] = v.y; qA[ks][2] = v.z; qA[ks][3] = v.w;
    }

    float O[4][4];
#pragma unroll
    for (int i = 0; i < 4; ++i)
#pragma unroll
        for (int j = 0; j < 4; ++j) O[i][j] = 0.f;
    float m0 = -1e30f, m1 = -1e30f, l0 = 0.f, l1 = 0.f;

    for (int tile = 0; tile < 16; ++tile) {
        __syncthreads();
        const float4* gk4 = (const float4*)g_k + (bh * 8192 + tile * 512);
        const float4* gv4 = (const float4*)g_v + (bh * 8192 + tile * 512);
#pragma unroll
        for (int u = 0; u < 4; ++u) {
            ((float4*)sK)[u * 128 + tid] = gk4[u * 128 + tid];
            ((float4*)sV)[u * 128 + tid] = gv4[u * 128 + tid];
        }
        __syncthreads();

        // ---- scores S = Q K^T (16 x 64), tf32 mma ----
        float cS[8][4];
#pragma unroll
        for (int nb = 0; nb < 8; ++nb) {
            cS[nb][0] = 0.f; cS[nb][1] = 0.f; cS[nb][2] = 0.f; cS[nb][3] = 0.f;
#pragma unroll
            for (int ks = 0; ks < 4; ++ks) {
                uint2 bb = ((const uint2*)sK)[(nb * 4 + ks) * 32 + lane];
                mma8(cS[nb], qA[ks], bb.x, bb.y);
            }
        }

        // ---- online softmax (base-2) ----
        float mt0 = fmaxf(cS[0][0], cS[0][1]);
        float mt1 = fmaxf(cS[0][2], cS[0][3]);
#pragma unroll
        for (int nb = 1; nb < 8; ++nb) {
            mt0 = fmaxf(mt0, fmaxf(cS[nb][0], cS[nb][1]));
            mt1 = fmaxf(mt1, fmaxf(cS[nb][2], cS[nb][3]));
        }
        mt0 = fmaxf(mt0, __shfl_xor_sync(0xffffffffu, mt0, 1));
        mt0 = fmaxf(mt0, __shfl_xor_sync(0xffffffffu, mt0, 2));
        mt1 = fmaxf(mt1, __shfl_xor_sync(0xffffffffu, mt1, 1));
        mt1 = fmaxf(mt1, __shfl_xor_sync(0xffffffffu, mt1, 2));
        float mn0 = fmaxf(m0, mt0), mn1 = fmaxf(m1, mt1);
        float corr0 = ex2f(m0 - mn0), corr1 = ex2f(m1 - mn1);
        m0 = mn0; m1 = mn1;

        float ps0 = 0.f, ps1 = 0.f;
#pragma unroll
        for (int nb = 0; nb < 8; ++nb) {
            cS[nb][0] = ex2f(cS[nb][0] - mn0); ps0 += cS[nb][0];
            cS[nb][1] = ex2f(cS[nb][1] - mn0); ps0 += cS[nb][1];
            cS[nb][2] = ex2f(cS[nb][2] - mn1); ps1 += cS[nb][2];
            cS[nb][3] = ex2f(cS[nb][3] - mn1); ps1 += cS[nb][3];
        }
        ps0 += __shfl_xor_sync(0xffffffffu, ps0, 1);
        ps0 += __shfl_xor_sync(0xffffffffu, ps0, 2);
        ps1 += __shfl_xor_sync(0xffffffffu, ps1, 1);
        ps1 += __shfl_xor_sync(0xffffffffu, ps1, 2);
        l0 = l0 * corr0 + ps0;
        l1 = l1 * corr1 + ps1;

#pragma unroll
        for (int nb = 0; nb < 4; ++nb) {
            O[nb][0] *= corr0; O[nb][1] *= corr0;
            O[nb][2] *= corr1; O[nb][3] *= corr1;
        }

        // ---- O += P V : rearrange P (C-layout) to A-fragments via shfl ----
        const int srcA = (lane & 28) + (tq >> 1);
        const int srcB = srcA + 2;
        const bool odd = tq & 1;
#pragma unroll
        for (int ks = 0; ks < 8; ++ks) {
            float p00 = __shfl_sync(0xffffffffu, cS[ks][0], srcA);
            float p01 = __shfl_sync(0xffffffffu, cS[ks][1], srcA);
            float p10 = __shfl_sync(0xffffffffu, cS[ks][2], srcA);
            float p11 = __shfl_sync(0xffffffffu, cS[ks][3], srcA);
            float p20 = __shfl_sync(0xffffffffu, cS[ks][0], srcB);
            float p21 = __shfl_sync(0xffffffffu, cS[ks][1], srcB);
            float p30 = __shfl_sync(0xffffffffu, cS[ks][2], srcB);
            float p31 = __shfl_sync(0xffffffffu, cS[ks][3], srcB);
            unsigned int aa[4];
            aa[0] = totf(odd ? p01 : p00);
            aa[1] = totf(odd ? p11 : p10);
            aa[2] = totf(odd ? p21 : p20);
            aa[3] = totf(odd ? p31 : p30);
#pragma unroll
            for (int nb = 0; nb < 4; ++nb) {
                uint2 bb = ((const uint2*)sV)[(ks * 4 + nb) * 32 + lane];
                mma8(O[nb], aa, bb.x, bb.y);
            }
        }
    }

    // ---- epilogue: normalize, write o to [B,T,E] re/im ----
    float inv0 = 1.f / l0, inv1 = 1.f / l1;
    int token0 = qb * 16 + g;
    int token1 = token0 + 8;
#pragma unroll
    for (int nb = 0; nb < 4; ++nb) {
        int c = nb * 8 + tq * 2;           // 0..31, pairs stay in same half
        float* base = (c < 16) ? g_or : g_oi;
        int cc = c & 15;
        float2 v0 = make_float2(O[nb][0] * inv0, O[nb][1] * inv0);
        float2 v1 = make_float2(O[nb][2] * inv1, O[nb][3] * inv1);
        *(float2*)(base + (b * TT + token0) * EE + h * DHD + cc) = v0;
        *(float2*)(base + (b * TT + token1) * EE + h * DHD + cc) = v1;
    }
}

// ---------------------------------------------------------------------------
// Kernel 3: y = o @ W2^T + b2 (complex), stored transposed to [2,B,E,T].
// ---------------------------------------------------------------------------
__global__ __launch_bounds__(256)
void out_kernel(float* __restrict__ out)
{
    __shared__ float sxr[16][68], sxi[16][68], swr[16][68], swi[16][68];

    const int m0 = blockIdx.x * 64;
    const int n0 = blockIdx.y * 64;
    const int b  = m0 >> 10;
    const int t0 = m0 & (TT - 1);
    const int tid = threadIdx.x;
    const int tx = tid & 15;       // token group (coalesced stores)
    const int ty = tid >> 4;       // output group

    float ar[4][4], ai[4][4];      // [token][out]
#pragma unroll
    for (int i = 0; i < 4; ++i)
#pragma unroll
        for (int j = 0; j < 4; ++j) { ar[i][j] = 0.f; ai[i][j] = 0.f; }

    for (int k0 = 0; k0 < EE; k0 += 16) {
        {
            int r = tid >> 2;
            int q = tid & 3;
            float4 a4 = *(const float4*)&g_or[(m0 + r) * EE + k0 + q * 4];
            float4 b4 = *(const float4*)&g_oi[(m0 + r) * EE + k0 + q * 4];
            sxr[q * 4 + 0][r] = a4.x; sxr[q * 4 + 1][r] = a4.y;
            sxr[q * 4 + 2][r] = a4.z; sxr[q * 4 + 3][r] = a4.w;
            sxi[q * 4 + 0][r] = b4.x; sxi[q * 4 + 1][r] = b4.y;
            sxi[q * 4 + 2][r] = b4.z; sxi[q * 4 + 3][r] = b4.w;
        }
        {
            int r = tid >> 2;
            int q = tid & 3;
            float4 a4 = *(const float4*)&g_W2r[(n0 + r) * EE + k0 + q * 4];
            float4 b4 = *(const float4*)&g_W2i[(n0 + r) * EE + k0 + q * 4];
            swr[q * 4 + 0][r] = a4.x; swr[q * 4 + 1][r] = a4.y;
            swr[q * 4 + 2][r] = a4.z; swr[q * 4 + 3][r] = a4.w;
            swi[q * 4 + 0][r] = b4.x; swi[q * 4 + 1][r] = b4.y;
            swi[q * 4 + 2][r] = b4.z; swi[q * 4 + 3][r] = b4.w;
        }
        __syncthreads();
#pragma unroll
        for (int kk = 0; kk < 16; ++kk) {
            float xr0[4], xi0[4], wr0[4], wi0[4];
#pragma unroll
            for (int u = 0; u < 4; ++u) {
                xr0[u] = sxr[kk][tx * 4 + u];   // per-lane tokens
                xi0[u] = sxi[kk][tx * 4 + u];
                wr0[u] = swr[kk][ty * 4 + u];   // broadcast outputs
                wi0[u] = swi[kk][ty * 4 + u];
            }
#pragma unroll
            for (int i = 0; i < 4; ++i)
#pragma unroll
                for (int j = 0; j < 4; ++j) {
                    ar[i][j] += xr0[i] * wr0[j] - xi0[i] * wi0[j];
                    ai[i][j] += xr0[i] * wi0[j] + xi0[i] * wr0[j];
                }
        }
        __syncthreads();
    }

    const int IM_OFF = BB * EE * TT;   // offset of imag component block
#pragma unroll
    for (int j = 0; j < 4; ++j) {
        int n = n0 + ty * 4 + j;
        float brr = g_b2r[n], bii = g_b2i[n];
        float4 vr = make_float4(ar[0][j] + brr, ar[1][j] + brr,
                                ar[2][j] + brr, ar[3][j] + brr);
        float4 vi = make_float4(ai[0][j] + bii, ai[1][j] + bii,
                                ai[2][j] + bii, ai[3][j] + bii);
        int t = t0 + tx * 4;
        float* pr = out + ((b * EE + n) * TT) + t;
        *(float4*)pr = vr;
        *(float4*)(pr + IM_OFF) = vi;
    }
}

// ---------------------------------------------------------------------------
extern "C" void kernel_launch(void* const* d_in, const int* in_sizes, int n_in,
                              void* d_out, int out_size)
{
    const float* xr  = (const float*)d_in[0];
    const float* xi  = (const float*)d_in[1];
    const float* wir = (const float*)d_in[2];
    const float* wii = (const float*)d_in[3];
    const float* bir = (const float*)d_in[4];
    const float* bii = (const float*)d_in[5];
    const float* wor = (const float*)d_in[6];
    const float* woi = (const float*)d_in[7];
    const float* bor = (const float*)d_in[8];
    const float* boi = (const float*)d_in[9];
    const float* wtr = (const float*)d_in[10];
    const float* wti = (const float*)d_in[11];
    const float* btr = (const float*)d_in[12];
    const float* bti = (const float*)d_in[13];

    combine_kernel<<<EE, EE>>>(wtr, wti, wor, woi, bor, boi, btr, bti);
    qkv_kernel<<<dim3((BB * TT) / 64, E3 / 64), 256>>>(xr, xi, wir, wii, bir, bii);
    attn_kernel<<<dim3(TT / 64, HH, BB), 128>>>();
    out_kernel<<<dim3((BB * TT) / 64, EE / 64), 256>>>((float*)d_out);
}

// round 7
// speedup vs baseline: 3.0080x; 1.5739x over previous
#include <cuda_runtime.h>
#include <cuda_bf16.h>

// Problem constants
#define BB 8
#define TT 1024
#define EE 128
#define HH 8
#define DHD 16
#define E3 384

// ---------------------------------------------------------------------------
// Scratch (allocation-free: __device__ globals)
// Q/K/V pre-swizzled into mma.m16n8k8 tf32 fragment layout per (b,h),
// logical [T,32]: cols 0..15 re, 16..31 im. Q carries 0.25*log2(e).
// ---------------------------------------------------------------------------
__device__ float g_q[BB * HH * TT * 32];
__device__ float g_k[BB * HH * TT * 32];
__device__ float g_v[BB * HH * TT * 32];
__device__ float g_or[BB * TT * EE];
__device__ float g_oi[BB * TT * EE];
__device__ float g_W2r[EE * EE];
__device__ float g_W2i[EE * EE];
__device__ float g_b2r[EE];
__device__ float g_b2i[EE];

__device__ __forceinline__ float ex2f(float x) {
    float r; asm("ex2.approx.ftz.f32 %0, %1;" : "=f"(r) : "f"(x)); return r;
}
__device__ __forceinline__ unsigned int totf(float x) {
    unsigned int u; asm("cvt.rna.tf32.f32 %0, %1;" : "=r"(u) : "f"(x)); return u;
}
__device__ __forceinline__ float totff(float x) {
    return __uint_as_float(totf(x));
}
__device__ __forceinline__ void mma8(float* d, const unsigned int* a,
                                     unsigned int b0, unsigned int b1) {
    asm volatile(
        "mma.sync.aligned.m16n8k8.row.col.f32.tf32.tf32.f32 "
        "{%0,%1,%2,%3},{%4,%5,%6,%7},{%8,%9},{%0,%1,%2,%3};"
        : "+f"(d[0]), "+f"(d[1]), "+f"(d[2]), "+f"(d[3])
        : "r"(a[0]), "r"(a[1]), "r"(a[2]), "r"(a[3]), "r"(b0), "r"(b1));
}

// ---------------------------------------------------------------------------
// Kernel 0: fold the two output linears into one.
//   W2 = wt @ wout   (complex [E,E]),  b2 = wt @ bout + bt
// ---------------------------------------------------------------------------
__global__ void combine_kernel(const float* __restrict__ wtr, const float* __restrict__ wti,
                               const float* __restrict__ wor, const float* __restrict__ woi,
                               const float* __restrict__ bor, const float* __restrict__ boi,
                               const float* __restrict__ btr, const float* __restrict__ bti)
{
    int j = blockIdx.x;      // 0..127
    int e = threadIdx.x;     // 0..127
    float accr = 0.f, acci = 0.f;
    for (int m = 0; m < EE; ++m) {
        float a = wtr[j * EE + m], c = wti[j * EE + m];
        float u = wor[m * EE + e], v = woi[m * EE + e];
        accr += a * u - c * v;
        acci += a * v + c * u;
    }
    g_W2r[j * EE + e] = accr;
    g_W2i[j * EE + e] = acci;
    if (e == 0) {
        float r = btr[j], im = bti[j];
        for (int m = 0; m < EE; ++m) {
            r  += wtr[j * EE + m] * bor[m] - wti[j * EE + m] * boi[m];
            im += wtr[j * EE + m] * boi[m] + wti[j * EE + m] * bor[m];
        }
        g_b2r[j] = r;
        g_b2i[j] = im;
    }
}

// ---------------------------------------------------------------------------
// Kernel 1: complex QKV projection on tensor cores (tf32 mma m16n8k8).
// Tile: 128 tokens x 64 outputs, 8 warps (4 m x 2 n), each warp 32x32.
// C_re = xr.wr + (-xi).wi ; C_im = xr.wi + xi.wr  (A frags shared, -xi is
// a sign-bit XOR). Operands tf32-rounded at smem store.
// Epilogue scatters into attention fragment layouts (+bias, Q scaled).
// ---------------------------------------------------------------------------
__global__ __launch_bounds__(256)
void qkv_kernel(const float* __restrict__ xr, const float* __restrict__ xi,
                const float* __restrict__ wre, const float* __restrict__ wim,
                const float* __restrict__ bre_g, const float* __restrict__ bim_g)
{
    __shared__ float sxr[16][136], sxi[16][136];  // [k][token], pad->bank-free
    __shared__ float swr[16][72],  swi[16][72];   // [k][out]

    const int m0 = blockIdx.x * 128;
    const int n0 = blockIdx.y * 64;
    const int b  = m0 >> 10;
    const int t0 = m0 & (TT - 1);
    const int tid = threadIdx.x;
    const int warp = tid >> 5, lane = tid & 31;
    const int g = lane >> 2, tq = lane & 3;
    const int wm = (warp & 3) * 32;
    const int wn = (warp >> 2) * 32;

    float Cre[2][4][4], Cim[2][4][4];
#pragma unroll
    for (int mi = 0; mi < 2; ++mi)
#pragma unroll
        for (int nj = 0; nj < 4; ++nj)
#pragma unroll
            for (int c = 0; c < 4; ++c) { Cre[mi][nj][c] = 0.f; Cim[mi][nj][c] = 0.f; }

    const float* xrb = xr + (long)b * EE * TT;
    const float* xib = xi + (long)b * EE * TT;

    for (int k0 = 0; k0 < EE; k0 += 16) {
#pragma unroll
        for (int u = 0; u < 8; ++u) {
            int li = u * 256 + tid;          // 0..2047
            int kk = li >> 7, mm = li & 127;
            sxr[kk][mm] = totff(xrb[(k0 + kk) * TT + t0 + mm]);
            sxi[kk][mm] = totff(xib[(k0 + kk) * TT + t0 + mm]);
        }
        {
            int r = tid >> 2, q = tid & 3;
            float4 a4 = *(const float4*)&wre[(n0 + r) * EE + k0 + q * 4];
            float4 b4 = *(const float4*)&wim[(n0 + r) * EE + k0 + q * 4];
            swr[q * 4 + 0][r] = totff(a4.x); swr[q * 4 + 1][r] = totff(a4.y);
            swr[q * 4 + 2][r] = totff(a4.z); swr[q * 4 + 3][r] = totff(a4.w);
            swi[q * 4 + 0][r] = totff(b4.x); swi[q * 4 + 1][r] = totff(b4.y);
            swi[q * 4 + 2][r] = totff(b4.z); swi[q * 4 + 3][r] = totff(b4.w);
        }
        __syncthreads();
#pragma unroll
        for (int k8 = 0; k8 < 16; k8 += 8) {
            unsigned int axr[2][4], axi[2][4], axin[2][4];
#pragma unroll
            for (int mi = 0; mi < 2; ++mi) {
                int tm = wm + mi * 16;
                axr[mi][0] = __float_as_uint(sxr[k8 + tq][tm + g]);
                axr[mi][1] = __float_as_uint(sxr[k8 + tq][tm + g + 8]);
                axr[mi][2] = __float_as_uint(sxr[k8 + tq + 4][tm + g]);
                axr[mi][3] = __float_as_uint(sxr[k8 + tq + 4][tm + g + 8]);
                axi[mi][0] = __float_as_uint(sxi[k8 + tq][tm + g]);
                axi[mi][1] = __float_as_uint(sxi[k8 + tq][tm + g + 8]);
                axi[mi][2] = __float_as_uint(sxi[k8 + tq + 4][tm + g]);
                axi[mi][3] = __float_as_uint(sxi[k8 + tq + 4][tm + g + 8]);
#pragma unroll
                for (int c = 0; c < 4; ++c) axin[mi][c] = axi[mi][c] ^ 0x80000000u;
            }
#pragma unroll
            for (int nj = 0; nj < 4; ++nj) {
                int tn = wn + nj * 8;
                unsigned int br0 = __float_as_uint(swr[k8 + tq][tn + g]);
                unsigned int br1 = __float_as_uint(swr[k8 + tq + 4][tn + g]);
                unsigned int bi0 = __float_as_uint(swi[k8 + tq][tn + g]);
                unsigned int bi1 = __float_as_uint(swi[k8 + tq + 4][tn + g]);
#pragma unroll
                for (int mi = 0; mi < 2; ++mi) {
                    mma8(Cre[mi][nj], axr[mi],  br0, br1);
                    mma8(Cre[mi][nj], axin[mi], bi0, bi1);
                    mma8(Cim[mi][nj], axr[mi],  bi0, bi1);
                    mma8(Cim[mi][nj], axi[mi],  br0, br1);
                }
            }
        }
        __syncthreads();
    }

    // Epilogue: bias + scatter into fragment-layout q/k/v (tf32-rounded)
    const float QS = 0.25f * 1.44269504088896f;   // DH^-0.5 * log2(e)
#pragma unroll
    for (int nj = 0; nj < 4; ++nj) {
#pragma unroll
        for (int cc = 0; cc < 2; ++cc) {
            int n = n0 + wn + nj * 8 + tq * 2 + cc;
            float bre = bre_g[n], bim = bim_g[n];
            int sec  = n >> 7;               // 0=q 1=k 2=v (uniform per CTA)
            int rloc = n & 127;
            int h = rloc >> 4, d = rloc & 15;
            int bh = b * HH + h;
#pragma unroll
            for (int mi = 0; mi < 2; ++mi) {
#pragma unroll
                for (int hh = 0; hh < 2; ++hh) {
                    int c = hh * 2 + cc;
                    int tloc = t0 + wm + mi * 16 + g + hh * 8;
                    float vr = Cre[mi][nj][c] + bre;
                    float vi = Cim[mi][nj][c] + bim;
                    if (sec == 0) {
                        vr *= QS; vi *= QS;
                        int qb = tloc >> 4, r = tloc & 15;
                        int gq = r & 7, hi = r >> 3;
#pragma unroll
                        for (int p = 0; p < 2; ++p) {
                            int col = d + p * 16;
                            float v = p ? vi : vr;
                            int ks = col >> 3, tl = col & 7;
                            int reg = ((tl & 4) >> 1) + hi;
                            int ln = gq * 4 + (tl & 3);
                            g_q[(((bh * 64 + qb) * 4 + ks) * 128) + ln * 4 + reg] =
                                __uint_as_float(totf(v));
                        }
                    } else if (sec == 1) {
                        int kb = tloc >> 3, gk = tloc & 7;
#pragma unroll
                        for (int p = 0; p < 2; ++p) {
                            int col = d + p * 16;
                            float v = p ? vi : vr;
                            int ks = col >> 3, tl = col & 7;
                            int jj = (tl >> 2) & 1;
                            int ln = gk * 4 + (tl & 3);
                            g_k[(((bh * 128 + kb) * 4 + ks) * 64) + ln * 2 + jj] =
                                __uint_as_float(totf(v));
                        }
                    } else {
                        int ksb = tloc >> 3, r = tloc & 7;
                        int jj = (r >> 2) & 1, tl = r & 3;
#pragma unroll
                        for (int p = 0; p < 2; ++p) {
                            int col = d + p * 16;
                            float v = p ? vi : vr;
                            int nb = col >> 3, gc = col & 7;
                            int ln = gc * 4 + tl;
                            g_v[(((bh * 128 + ksb) * 4 + nb) * 64) + ln * 2 + jj] =
                                __uint_as_float(totf(v));
                        }
                    }
                }
            }
        }
    }
}

// ---------------------------------------------------------------------------
// Kernel 2: flash attention on tensor cores (tf32 mma m16n8k8). Unchanged.
// ---------------------------------------------------------------------------
__global__ __launch_bounds__(128)
void attn_kernel()
{
    __shared__ float sK[2048];
    __shared__ float sV[2048];

    const int b = blockIdx.z, h = blockIdx.y;
    const int bh = b * HH + h;
    const int tid = threadIdx.x;
    const int warp = tid >> 5, lane = tid & 31;
    const int g = lane >> 2, tq = lane & 3;
    const int qb = blockIdx.x * 4 + warp;

    unsigned int qA[4][4];
#pragma unroll
    for (int ks = 0; ks < 4; ++ks) {
        uint4 v = ((const uint4*)g_q)[((bh * 64 + qb) * 4 + ks) * 32 + lane];
        qA[ks][0] = v.x; qA[ks][1] = v.y; qA[ks][2] = v.z; qA[ks][3] = v.w;
    }

    float O[4][4];
#pragma unroll
    for (int i = 0; i < 4; ++i)
#pragma unroll
        for (int j = 0; j < 4; ++j) O[i][j] = 0.f;
    float m0 = -1e30f, m1 = -1e30f, l0 = 0.f, l1 = 0.f;

    for (int tile = 0; tile < 16; ++tile) {
        __syncthreads();
        const float4* gk4 = (const float4*)g_k + (bh * 8192 + tile * 512);
        const float4* gv4 = (const float4*)g_v + (bh * 8192 + tile * 512);
#pragma unroll
        for (int u = 0; u < 4; ++u) {
            ((float4*)sK)[u * 128 + tid] = gk4[u * 128 + tid];
            ((float4*)sV)[u * 128 + tid] = gv4[u * 128 + tid];
        }
        __syncthreads();

        float cS[8][4];
#pragma unroll
        for (int nb = 0; nb < 8; ++nb) {
            cS[nb][0] = 0.f; cS[nb][1] = 0.f; cS[nb][2] = 0.f; cS[nb][3] = 0.f;
#pragma unroll
            for (int ks = 0; ks < 4; ++ks) {
                uint2 bb = ((const uint2*)sK)[(nb * 4 + ks) * 32 + lane];
                mma8(cS[nb], qA[ks], bb.x, bb.y);
            }
        }

        float mt0 = fmaxf(cS[0][0], cS[0][1]);
        float mt1 = fmaxf(cS[0][2], cS[0][3]);
#pragma unroll
        for (int nb = 1; nb < 8; ++nb) {
            mt0 = fmaxf(mt0, fmaxf(cS[nb][0], cS[nb][1]));
            mt1 = fmaxf(mt1, fmaxf(cS[nb][2], cS[nb][3]));
        }
        mt0 = fmaxf(mt0, __shfl_xor_sync(0xffffffffu, mt0, 1));
        mt0 = fmaxf(mt0, __shfl_xor_sync(0xffffffffu, mt0, 2));
        mt1 = fmaxf(mt1, __shfl_xor_sync(0xffffffffu, mt1, 1));
        mt1 = fmaxf(mt1, __shfl_xor_sync(0xffffffffu, mt1, 2));
        float mn0 = fmaxf(m0, mt0), mn1 = fmaxf(m1, mt1);
        float corr0 = ex2f(m0 - mn0), corr1 = ex2f(m1 - mn1);
        m0 = mn0; m1 = mn1;

        float ps0 = 0.f, ps1 = 0.f;
#pragma unroll
        for (int nb = 0; nb < 8; ++nb) {
            cS[nb][0] = ex2f(cS[nb][0] - mn0); ps0 += cS[nb][0];
            cS[nb][1] = ex2f(cS[nb][1] - mn0); ps0 += cS[nb][1];
            cS[nb][2] = ex2f(cS[nb][2] - mn1); ps1 += cS[nb][2];
            cS[nb][3] = ex2f(cS[nb][3] - mn1); ps1 += cS[nb][3];
        }
        ps0 += __shfl_xor_sync(0xffffffffu, ps0, 1);
        ps0 += __shfl_xor_sync(0xffffffffu, ps0, 2);
        ps1 += __shfl_xor_sync(0xffffffffu, ps1, 1);
        ps1 += __shfl_xor_sync(0xffffffffu, ps1, 2);
        l0 = l0 * corr0 + ps0;
        l1 = l1 * corr1 + ps1;

#pragma unroll
        for (int nb = 0; nb < 4; ++nb) {
            O[nb][0] *= corr0; O[nb][1] *= corr0;
            O[nb][2] *= corr1; O[nb][3] *= corr1;
        }

        const int srcA = (lane & 28) + (tq >> 1);
        const int srcB = srcA + 2;
        const bool odd = tq & 1;
#pragma unroll
        for (int ks = 0; ks < 8; ++ks) {
            float p00 = __shfl_sync(0xffffffffu, cS[ks][0], srcA);
            float p01 = __shfl_sync(0xffffffffu, cS[ks][1], srcA);
            float p10 = __shfl_sync(0xffffffffu, cS[ks][2], srcA);
            float p11 = __shfl_sync(0xffffffffu, cS[ks][3], srcA);
            float p20 = __shfl_sync(0xffffffffu, cS[ks][0], srcB);
            float p21 = __shfl_sync(0xffffffffu, cS[ks][1], srcB);
            float p30 = __shfl_sync(0xffffffffu, cS[ks][2], srcB);
            float p31 = __shfl_sync(0xffffffffu, cS[ks][3], srcB);
            unsigned int aa[4];
            aa[0] = totf(odd ? p01 : p00);
            aa[1] = totf(odd ? p11 : p10);
            aa[2] = totf(odd ? p21 : p20);
            aa[3] = totf(odd ? p31 : p30);
#pragma unroll
            for (int nb = 0; nb < 4; ++nb) {
                uint2 bb = ((const uint2*)sV)[(ks * 4 + nb) * 32 + lane];
                mma8(O[nb], aa, bb.x, bb.y);
            }
        }
    }

    float inv0 = 1.f / l0, inv1 = 1.f / l1;
    int token0 = qb * 16 + g;
    int token1 = token0 + 8;
#pragma unroll
    for (int nb = 0; nb < 4; ++nb) {
        int c = nb * 8 + tq * 2;
        float* base = (c < 16) ? g_or : g_oi;
        int cc = c & 15;
        float2 v0 = make_float2(O[nb][0] * inv0, O[nb][1] * inv0);
        float2 v1 = make_float2(O[nb][2] * inv1, O[nb][3] * inv1);
        *(float2*)(base + (b * TT + token0) * EE + h * DHD + cc) = v0;
        *(float2*)(base + (b * TT + token1) * EE + h * DHD + cc) = v1;
    }
}

// ---------------------------------------------------------------------------
// Kernel 3: y = o @ W2^T + b2 (complex) on tensor cores, stored to [2,B,E,T].
// Same warp tiling as qkv. Epilogue stores along T (8-consecutive chunks).
// ---------------------------------------------------------------------------
__global__ __launch_bounds__(256)
void out_kernel(float* __restrict__ out)
{
    __shared__ float sar[16][136], sai[16][136];  // [k][token]
    __shared__ float swr[16][72],  swi[16][72];   // [k][out]

    const int m0 = blockIdx.x * 128;
    const int n0 = blockIdx.y * 64;
    const int b  = m0 >> 10;
    const int t0 = m0 & (TT - 1);
    const int tid = threadIdx.x;
    const int warp = tid >> 5, lane = tid & 31;
    const int g = lane >> 2, tq = lane & 3;
    const int wm = (warp & 3) * 32;
    const int wn = (warp >> 2) * 32;

    float Cre[2][4][4], Cim[2][4][4];
#pragma unroll
    for (int mi = 0; mi < 2; ++mi)
#pragma unroll
        for (int nj = 0; nj < 4; ++nj)
#pragma unroll
            for (int c = 0; c < 4; ++c) { Cre[mi][nj][c] = 0.f; Cim[mi][nj][c] = 0.f; }

    for (int k0 = 0; k0 < EE; k0 += 16) {
#pragma unroll
        for (int u = 0; u < 2; ++u) {
            int li = u * 256 + tid;       // 0..511
            int r = li >> 2, q = li & 3;  // token row, float4 idx
            float4 a4 = *(const float4*)&g_or[(m0 + r) * EE + k0 + q * 4];
            float4 b4 = *(const float4*)&g_oi[(m0 + r) * EE + k0 + q * 4];
            sar[q * 4 + 0][r] = totff(a4.x); sar[q * 4 + 1][r] = totff(a4.y);
            sar[q * 4 + 2][r] = totff(a4.z); sar[q * 4 + 3][r] = totff(a4.w);
            sai[q * 4 + 0][r] = totff(b4.x); sai[q * 4 + 1][r] = totff(b4.y);
            sai[q * 4 + 2][r] = totff(b4.z); sai[q * 4 + 3][r] = totff(b4.w);
        }
        {
            int r = tid >> 2, q = tid & 3;
            float4 a4 = *(const float4*)&g_W2r[(n0 + r) * EE + k0 + q * 4];
            float4 b4 = *(const float4*)&g_W2i[(n0 + r) * EE + k0 + q * 4];
            swr[q * 4 + 0][r] = totff(a4.x); swr[q * 4 + 1][r] = totff(a4.y);
            swr[q * 4 + 2][r] = totff(a4.z); swr[q * 4 + 3][r] = totff(a4.w);
            swi[q * 4 + 0][r] = totff(b4.x); swi[q * 4 + 1][r] = totff(b4.y);
            swi[q * 4 + 2][r] = totff(b4.z); swi[q * 4 + 3][r] = totff(b4.w);
        }
        __syncthreads();
#pragma unroll
        for (int k8 = 0; k8 < 16; k8 += 8) {
            unsigned int axr[2][4], axi[2][4], axin[2][4];
#pragma unroll
            for (int mi = 0; mi < 2; ++mi) {
                int tm = wm + mi * 16;
                axr[mi][0] = __float_as_uint(sar[k8 + tq][tm + g]);
                axr[mi][1] = __float_as_uint(sar[k8 + tq][tm + g + 8]);
                axr[mi][2] = __float_as_uint(sar[k8 + tq + 4][tm + g]);
                axr[mi][3] = __float_as_uint(sar[k8 + tq + 4][tm + g + 8]);
                axi[mi][0] = __float_as_uint(sai[k8 + tq][tm + g]);
                axi[mi][1] = __float_as_uint(sai[k8 + tq][tm + g + 8]);
                axi[mi][2] = __float_as_uint(sai[k8 + tq + 4][tm + g]);
                axi[mi][3] = __float_as_uint(sai[k8 + tq + 4][tm + g + 8]);
#pragma unroll
                for (int c = 0; c < 4; ++c) axin[mi][c] = axi[mi][c] ^ 0x80000000u;
            }
#pragma unroll
            for (int nj = 0; nj < 4; ++nj) {
                int tn = wn + nj * 8;
                unsigned int br0 = __float_as_uint(swr[k8 + tq][tn + g]);
                unsigned int br1 = __float_as_uint(swr[k8 + tq + 4][tn + g]);
                unsigned int bi0 = __float_as_uint(swi[k8 + tq][tn + g]);
                unsigned int bi1 = __float_as_uint(swi[k8 + tq + 4][tn + g]);
#pragma unroll
                for (int mi = 0; mi < 2; ++mi) {
                    mma8(Cre[mi][nj], axr[mi],  br0, br1);
                    mma8(Cre[mi][nj], axin[mi], bi0, bi1);
                    mma8(Cim[mi][nj], axr[mi],  bi0, bi1);
                    mma8(Cim[mi][nj], axi[mi],  br0, br1);
                }
            }
        }
        __syncthreads();
    }

    const int IM_OFF = BB * EE * TT;
#pragma unroll
    for (int nj = 0; nj < 4; ++nj) {
#pragma unroll
        for (int cc = 0; cc < 2; ++cc) {
            int n = n0 + wn + nj * 8 + tq * 2 + cc;
            float brr = g_b2r[n], bii = g_b2i[n];
            float* pr = out + ((b * EE + n) * TT);
#pragma unroll
            for (int mi = 0; mi < 2; ++mi) {
#pragma unroll
                for (int hh = 0; hh < 2; ++hh) {
                    int c = hh * 2 + cc;
                    int t = t0 + wm + mi * 16 + g + hh * 8;
                    pr[t]          = Cre[mi][nj][c] + brr;
                    pr[t + IM_OFF] = Cim[mi][nj][c] + bii;
                }
            }
        }
    }
}

// ---------------------------------------------------------------------------
extern "C" void kernel_launch(void* const* d_in, const int* in_sizes, int n_in,
                              void* d_out, int out_size)
{
    const float* xr  = (const float*)d_in[0];
    const float* xi  = (const float*)d_in[1];
    const float* wir = (const float*)d_in[2];
    const float* wii = (const float*)d_in[3];
    const float* bir = (const float*)d_in[4];
    const float* bii = (const float*)d_in[5];
    const float* wor = (const float*)d_in[6];
    const float* woi = (const float*)d_in[7];
    const float* bor = (const float*)d_in[8];
    const float* boi = (const float*)d_in[9];
    const float* wtr = (const float*)d_in[10];
    const float* wti = (const float*)d_in[11];
    const float* btr = (const float*)d_in[12];
    const float* bti = (const float*)d_in[13];

    combine_kernel<<<EE, EE>>>(wtr, wti, wor, woi, bor, boi, btr, bti);
    qkv_kernel<<<dim3((BB * TT) / 128, E3 / 64), 256>>>(xr, xi, wir, wii, bir, bii);
    attn_kernel<<<dim3(TT / 64, HH, BB), 128>>>();
    out_kernel<<<dim3((BB * TT) / 128, EE / 64), 256>>>((float*)d_out);
}

// round 8
// speedup vs baseline: 3.3137x; 1.1016x over previous
#include <cuda_runtime.h>
#include <cuda_bf16.h>

// Problem constants
#define BB 8
#define TT 1024
#define EE 128
#define HH 8
#define DHD 16
#define E3 384

// ---------------------------------------------------------------------------
// Scratch (allocation-free: __device__ globals)
// Q/K/V pre-swizzled into mma.m16n8k8 tf32 fragment layout per (b,h),
// logical [T,32]: cols 0..15 re, 16..31 im. Q carries 0.25*log2(e).
// V fragments additionally permute keys within each 8-group by
// pi(s)=2s (s<4), 2(s-4)+1 (s>=4) so the S-accumulator C-layout maps to the
// PV A-fragment by pure register renaming (no shuffles).
// ---------------------------------------------------------------------------
__device__ float g_q[BB * HH * TT * 32];
__device__ float g_k[BB * HH * TT * 32];
__device__ float g_v[BB * HH * TT * 32];
__device__ float g_or[BB * TT * EE];
__device__ float g_oi[BB * TT * EE];
__device__ float g_W2r[EE * EE];
__device__ float g_W2i[EE * EE];
__device__ float g_b2r[EE];
__device__ float g_b2i[EE];

__device__ __forceinline__ float ex2f(float x) {
    float r; asm("ex2.approx.ftz.f32 %0, %1;" : "=f"(r) : "f"(x)); return r;
}
__device__ __forceinline__ unsigned int totf(float x) {
    unsigned int u; asm("cvt.rna.tf32.f32 %0, %1;" : "=r"(u) : "f"(x)); return u;
}
__device__ __forceinline__ float totff(float x) {
    return __uint_as_float(totf(x));
}
__device__ __forceinline__ void mma8(float* d, const unsigned int* a,
                                     unsigned int b0, unsigned int b1) {
    asm volatile(
        "mma.sync.aligned.m16n8k8.row.col.f32.tf32.tf32.f32 "
        "{%0,%1,%2,%3},{%4,%5,%6,%7},{%8,%9},{%0,%1,%2,%3};"
        : "+f"(d[0]), "+f"(d[1]), "+f"(d[2]), "+f"(d[3])
        : "r"(a[0]), "r"(a[1]), "r"(a[2]), "r"(a[3]), "r"(b0), "r"(b1));
}

// ---------------------------------------------------------------------------
// Kernel 0: fold the two output linears into one.
//   W2 = wt @ wout   (complex [E,E]),  b2 = wt @ bout + bt
// ---------------------------------------------------------------------------
__global__ void combine_kernel(const float* __restrict__ wtr, const float* __restrict__ wti,
                               const float* __restrict__ wor, const float* __restrict__ woi,
                               const float* __restrict__ bor, const float* __restrict__ boi,
                               const float* __restrict__ btr, const float* __restrict__ bti)
{
    int j = blockIdx.x;      // 0..127
    int e = threadIdx.x;     // 0..127
    float accr = 0.f, acci = 0.f;
    for (int m = 0; m < EE; ++m) {
        float a = wtr[j * EE + m], c = wti[j * EE + m];
        float u = wor[m * EE + e], v = woi[m * EE + e];
        accr += a * u - c * v;
        acci += a * v + c * u;
    }
    g_W2r[j * EE + e] = accr;
    g_W2i[j * EE + e] = acci;
    if (e == 0) {
        float r = btr[j], im = bti[j];
        for (int m = 0; m < EE; ++m) {
            r  += wtr[j * EE + m] * bor[m] - wti[j * EE + m] * boi[m];
            im += wtr[j * EE + m] * boi[m] + wti[j * EE + m] * bor[m];
        }
        g_b2r[j] = r;
        g_b2i[j] = im;
    }
}

// ---------------------------------------------------------------------------
// Kernel 1: complex QKV projection on tensor cores (tf32 mma m16n8k8).
// Tile: 128 tokens x 64 outputs, 8 warps (4 m x 2 n), each warp 32x32.
// Epilogue scatters into attention fragment layouts (+bias, Q scaled;
// V uses the pi-permuted key slots).
// ---------------------------------------------------------------------------
__global__ __launch_bounds__(256)
void qkv_kernel(const float* __restrict__ xr, const float* __restrict__ xi,
                const float* __restrict__ wre, const float* __restrict__ wim,
                const float* __restrict__ bre_g, const float* __restrict__ bim_g)
{
    __shared__ float sxr[16][136], sxi[16][136];  // [k][token], pad->bank-free
    __shared__ float swr[16][72],  swi[16][72];   // [k][out]

    const int m0 = blockIdx.x * 128;
    const int n0 = blockIdx.y * 64;
    const int b  = m0 >> 10;
    const int t0 = m0 & (TT - 1);
    const int tid = threadIdx.x;
    const int warp = tid >> 5, lane = tid & 31;
    const int g = lane >> 2, tq = lane & 3;
    const int wm = (warp & 3) * 32;
    const int wn = (warp >> 2) * 32;

    float Cre[2][4][4], Cim[2][4][4];
#pragma unroll
    for (int mi = 0; mi < 2; ++mi)
#pragma unroll
        for (int nj = 0; nj < 4; ++nj)
#pragma unroll
            for (int c = 0; c < 4; ++c) { Cre[mi][nj][c] = 0.f; Cim[mi][nj][c] = 0.f; }

    const float* xrb = xr + (long)b * EE * TT;
    const float* xib = xi + (long)b * EE * TT;

    for (int k0 = 0; k0 < EE; k0 += 16) {
#pragma unroll
        for (int u = 0; u < 8; ++u) {
            int li = u * 256 + tid;          // 0..2047
            int kk = li >> 7, mm = li & 127;
            sxr[kk][mm] = totff(xrb[(k0 + kk) * TT + t0 + mm]);
            sxi[kk][mm] = totff(xib[(k0 + kk) * TT + t0 + mm]);
        }
        {
            int r = tid >> 2, q = tid & 3;
            float4 a4 = *(const float4*)&wre[(n0 + r) * EE + k0 + q * 4];
            float4 b4 = *(const float4*)&wim[(n0 + r) * EE + k0 + q * 4];
            swr[q * 4 + 0][r] = totff(a4.x); swr[q * 4 + 1][r] = totff(a4.y);
            swr[q * 4 + 2][r] = totff(a4.z); swr[q * 4 + 3][r] = totff(a4.w);
            swi[q * 4 + 0][r] = totff(b4.x); swi[q * 4 + 1][r] = totff(b4.y);
            swi[q * 4 + 2][r] = totff(b4.z); swi[q * 4 + 3][r] = totff(b4.w);
        }
        __syncthreads();
#pragma unroll
        for (int k8 = 0; k8 < 16; k8 += 8) {
            unsigned int axr[2][4], axi[2][4], axin[2][4];
#pragma unroll
            for (int mi = 0; mi < 2; ++mi) {
                int tm = wm + mi * 16;
                axr[mi][0] = __float_as_uint(sxr[k8 + tq][tm + g]);
                axr[mi][1] = __float_as_uint(sxr[k8 + tq][tm + g + 8]);
                axr[mi][2] = __float_as_uint(sxr[k8 + tq + 4][tm + g]);
                axr[mi][3] = __float_as_uint(sxr[k8 + tq + 4][tm + g + 8]);
                axi[mi][0] = __float_as_uint(sxi[k8 + tq][tm + g]);
                axi[mi][1] = __float_as_uint(sxi[k8 + tq][tm + g + 8]);
                axi[mi][2] = __float_as_uint(sxi[k8 + tq + 4][tm + g]);
                axi[mi][3] = __float_as_uint(sxi[k8 + tq + 4][tm + g + 8]);
#pragma unroll
                for (int c = 0; c < 4; ++c) axin[mi][c] = axi[mi][c] ^ 0x80000000u;
            }
#pragma unroll
            for (int nj = 0; nj < 4; ++nj) {
                int tn = wn + nj * 8;
                unsigned int br0 = __float_as_uint(swr[k8 + tq][tn + g]);
                unsigned int br1 = __float_as_uint(swr[k8 + tq + 4][tn + g]);
                unsigned int bi0 = __float_as_uint(swi[k8 + tq][tn + g]);
                unsigned int bi1 = __float_as_uint(swi[k8 + tq + 4][tn + g]);
#pragma unroll
                for (int mi = 0; mi < 2; ++mi) {
                    mma8(Cre[mi][nj], axr[mi],  br0, br1);
                    mma8(Cre[mi][nj], axin[mi], bi0, bi1);
                    mma8(Cim[mi][nj], axr[mi],  bi0, bi1);
                    mma8(Cim[mi][nj], axi[mi],  br0, br1);
                }
            }
        }
        __syncthreads();
    }

    // Epilogue: bias + scatter into fragment-layout q/k/v (tf32-rounded)
    const float QS = 0.25f * 1.44269504088896f;   // DH^-0.5 * log2(e)
#pragma unroll
    for (int nj = 0; nj < 4; ++nj) {
#pragma unroll
        for (int cc = 0; cc < 2; ++cc) {
            int n = n0 + wn + nj * 8 + tq * 2 + cc;
            float bre = bre_g[n], bim = bim_g[n];
            int sec  = n >> 7;               // 0=q 1=k 2=v (uniform per CTA)
            int rloc = n & 127;
            int h = rloc >> 4, d = rloc & 15;
            int bh = b * HH + h;
#pragma unroll
            for (int mi = 0; mi < 2; ++mi) {
#pragma unroll
                for (int hh = 0; hh < 2; ++hh) {
                    int c = hh * 2 + cc;
                    int tloc = t0 + wm + mi * 16 + g + hh * 8;
                    float vr = Cre[mi][nj][c] + bre;
                    float vi = Cim[mi][nj][c] + bim;
                    if (sec == 0) {
                        vr *= QS; vi *= QS;
                        int qb = tloc >> 4, r = tloc & 15;
                        int gq = r & 7, hi = r >> 3;
#pragma unroll
                        for (int p = 0; p < 2; ++p) {
                            int col = d + p * 16;
                            float v = p ? vi : vr;
                            int ks = col >> 3, tl = col & 7;
                            int reg = ((tl & 4) >> 1) + hi;
                            int ln = gq * 4 + (tl & 3);
                            g_q[(((bh * 64 + qb) * 4 + ks) * 128) + ln * 4 + reg] =
                                __uint_as_float(totf(v));
                        }
                    } else if (sec == 1) {
                        int kb = tloc >> 3, gk = tloc & 7;
#pragma unroll
                        for (int p = 0; p < 2; ++p) {
                            int col = d + p * 16;
                            float v = p ? vi : vr;
                            int ks = col >> 3, tl = col & 7;
                            int jj = (tl >> 2) & 1;
                            int ln = gk * 4 + (tl & 3);
                            g_k[(((bh * 128 + kb) * 4 + ks) * 64) + ln * 2 + jj] =
                                __uint_as_float(totf(v));
                        }
                    } else {
                        // V: key r within 8-group goes to slot s = pi^-1(r):
                        //   jj = s>=4 = r&1 ;  tl = s&3 = r>>1
                        int ksb = tloc >> 3, r = tloc & 7;
                        int jj = r & 1, tl = r >> 1;
#pragma unroll
                        for (int p = 0; p < 2; ++p) {
                            int col = d + p * 16;
                            float v = p ? vi : vr;
                            int nb = col >> 3, gc = col & 7;
                            int ln = gc * 4 + tl;
                            g_v[(((bh * 128 + ksb) * 4 + nb) * 64) + ln * 2 + jj] =
                                __uint_as_float(totf(v));
                        }
                    }
                }
            }
        }
    }
}

// ---------------------------------------------------------------------------
// Kernel 2: flash attention on tensor cores (tf32 mma m16n8k8).
// P->A fragment conversion is a register rename thanks to pi-permuted V:
//   a0=c0, a1=c2, a2=c1, a3=c3  (no shuffles).
// ---------------------------------------------------------------------------
__global__ __launch_bounds__(128)
void attn_kernel()
{
    __shared__ float sK[2048];
    __shared__ float sV[2048];

    const int b = blockIdx.z, h = blockIdx.y;
    const int bh = b * HH + h;
    const int tid = threadIdx.x;
    const int warp = tid >> 5, lane = tid & 31;
    const int g = lane >> 2, tq = lane & 3;
    const int qb = blockIdx.x * 4 + warp;

    unsigned int qA[4][4];
#pragma unroll
    for (int ks = 0; ks < 4; ++ks) {
        uint4 v = ((const uint4*)g_q)[((bh * 64 + qb) * 4 + ks) * 32 + lane];
        qA[ks][0] = v.x; qA[ks][1] = v.y; qA[ks][2] = v.z; qA[ks][3] = v.w;
    }

    float O[4][4];
#pragma unroll
    for (int i = 0; i < 4; ++i)
#pragma unroll
        for (int j = 0; j < 4; ++j) O[i][j] = 0.f;
    float m0 = -1e30f, m1 = -1e30f, l0 = 0.f, l1 = 0.f;

    for (int tile = 0; tile < 16; ++tile) {
        __syncthreads();
        const float4* gk4 = (const float4*)g_k + (bh * 8192 + tile * 512);
        const float4* gv4 = (const float4*)g_v + (bh * 8192 + tile * 512);
#pragma unroll
        for (int u = 0; u < 4; ++u) {
            ((float4*)sK)[u * 128 + tid] = gk4[u * 128 + tid];
            ((float4*)sV)[u * 128 + tid] = gv4[u * 128 + tid];
        }
        __syncthreads();

        float cS[8][4];
#pragma unroll
        for (int nb = 0; nb < 8; ++nb) {
            cS[nb][0] = 0.f; cS[nb][1] = 0.f; cS[nb][2] = 0.f; cS[nb][3] = 0.f;
#pragma unroll
            for (int ks = 0; ks < 4; ++ks) {
                uint2 bb = ((const uint2*)sK)[(nb * 4 + ks) * 32 + lane];
                mma8(cS[nb], qA[ks], bb.x, bb.y);
            }
        }

        float mt0 = fmaxf(cS[0][0], cS[0][1]);
        float mt1 = fmaxf(cS[0][2], cS[0][3]);
#pragma unroll
        for (int nb = 1; nb < 8; ++nb) {
            mt0 = fmaxf(mt0, fmaxf(cS[nb][0], cS[nb][1]));
            mt1 = fmaxf(mt1, fmaxf(cS[nb][2], cS[nb][3]));
        }
        mt0 = fmaxf(mt0, __shfl_xor_sync(0xffffffffu, mt0, 1));
        mt0 = fmaxf(mt0, __shfl_xor_sync(0xffffffffu, mt0, 2));
        mt1 = fmaxf(mt1, __shfl_xor_sync(0xffffffffu, mt1, 1));
        mt1 = fmaxf(mt1, __shfl_xor_sync(0xffffffffu, mt1, 2));
        float mn0 = fmaxf(m0, mt0), mn1 = fmaxf(m1, mt1);
        float corr0 = ex2f(m0 - mn0), corr1 = ex2f(m1 - mn1);
        m0 = mn0; m1 = mn1;

        float ps0 = 0.f, ps1 = 0.f;
#pragma unroll
        for (int nb = 0; nb < 8; ++nb) {
            cS[nb][0] = ex2f(cS[nb][0] - mn0); ps0 += cS[nb][0];
            cS[nb][1] = ex2f(cS[nb][1] - mn0); ps0 += cS[nb][1];
            cS[nb][2] = ex2f(cS[nb][2] - mn1); ps1 += cS[nb][2];
            cS[nb][3] = ex2f(cS[nb][3] - mn1); ps1 += cS[nb][3];
        }
        ps0 += __shfl_xor_sync(0xffffffffu, ps0, 1);
        ps0 += __shfl_xor_sync(0xffffffffu, ps0, 2);
        ps1 += __shfl_xor_sync(0xffffffffu, ps1, 1);
        ps1 += __shfl_xor_sync(0xffffffffu, ps1, 2);
        l0 = l0 * corr0 + ps0;
        l1 = l1 * corr1 + ps1;

#pragma unroll
        for (int nb = 0; nb < 4; ++nb) {
            O[nb][0] *= corr0; O[nb][1] *= corr0;
            O[nb][2] *= corr1; O[nb][3] *= corr1;
        }

        // ---- O += P V : A-frag = renamed C-frag (pi-permuted V rows) ----
#pragma unroll
        for (int ks = 0; ks < 8; ++ks) {
            unsigned int aa[4];
            aa[0] = totf(cS[ks][0]);
            aa[1] = totf(cS[ks][2]);
            aa[2] = totf(cS[ks][1]);
            aa[3] = totf(cS[ks][3]);
#pragma unroll
            for (int nb = 0; nb < 4; ++nb) {
                uint2 bb = ((const uint2*)sV)[(ks * 4 + nb) * 32 + lane];
                mma8(O[nb], aa, bb.x, bb.y);
            }
        }
    }

    float inv0 = 1.f / l0, inv1 = 1.f / l1;
    int token0 = qb * 16 + g;
    int token1 = token0 + 8;
#pragma unroll
    for (int nb = 0; nb < 4; ++nb) {
        int c = nb * 8 + tq * 2;
        float* base = (c < 16) ? g_or : g_oi;
        int cc = c & 15;
        float2 v0 = make_float2(O[nb][0] * inv0, O[nb][1] * inv0);
        float2 v1 = make_float2(O[nb][2] * inv1, O[nb][3] * inv1);
        *(float2*)(base + (b * TT + token0) * EE + h * DHD + cc) = v0;
        *(float2*)(base + (b * TT + token1) * EE + h * DHD + cc) = v1;
    }
}

// ---------------------------------------------------------------------------
// Kernel 3: y = o @ W2^T + b2 (complex) on tensor cores, stored to [2,B,E,T].
// 64-token x 64-output tiles, 4 warps (2 m x 2 n) -> 256 CTAs for better
// SM coverage / latency hiding (R7: 128 CTAs, issue=17.6%).
// ---------------------------------------------------------------------------
__global__ __launch_bounds__(128)
void out_kernel(float* __restrict__ out)
{
    __shared__ float sar[16][72], sai[16][72];   // [k][token]
    __shared__ float swr[16][72], swi[16][72];   // [k][out]

    const int m0 = blockIdx.x * 64;
    const int n0 = blockIdx.y * 64;
    const int b  = m0 >> 10;
    const int t0 = m0 & (TT - 1);
    const int tid = threadIdx.x;
    const int warp = tid >> 5, lane = tid & 31;
    const int g = lane >> 2, tq = lane & 3;
    const int wm = (warp & 1) * 32;
    const int wn = (warp >> 1) * 32;

    float Cre[2][4][4], Cim[2][4][4];
#pragma unroll
    for (int mi = 0; mi < 2; ++mi)
#pragma unroll
        for (int nj = 0; nj < 4; ++nj)
#pragma unroll
            for (int c = 0; c < 4; ++c) { Cre[mi][nj][c] = 0.f; Cim[mi][nj][c] = 0.f; }

    for (int k0 = 0; k0 < EE; k0 += 16) {
#pragma unroll
        for (int u = 0; u < 2; ++u) {
            int li = u * 128 + tid;       // 0..255
            int r = li >> 2, q = li & 3;  // token row, float4 idx
            float4 a4 = *(const float4*)&g_or[(m0 + r) * EE + k0 + q * 4];
            float4 b4 = *(const float4*)&g_oi[(m0 + r) * EE + k0 + q * 4];
            sar[q * 4 + 0][r] = totff(a4.x); sar[q * 4 + 1][r] = totff(a4.y);
            sar[q * 4 + 2][r] = totff(a4.z); sar[q * 4 + 3][r] = totff(a4.w);
            sai[q * 4 + 0][r] = totff(b4.x); sai[q * 4 + 1][r] = totff(b4.y);
            sai[q * 4 + 2][r] = totff(b4.z); sai[q * 4 + 3][r] = totff(b4.w);
        }
#pragma unroll
        for (int u = 0; u < 2; ++u) {
            int li = u * 128 + tid;
            int r = li >> 2, q = li & 3;  // output row, float4 idx
            float4 a4 = *(const float4*)&g_W2r[(n0 + r) * EE + k0 + q * 4];
            float4 b4 = *(const float4*)&g_W2i[(n0 + r) * EE + k0 + q * 4];
            swr[q * 4 + 0][r] = totff(a4.x); swr[q * 4 + 1][r] = totff(a4.y);
            swr[q * 4 + 2][r] = totff(a4.z); swr[q * 4 + 3][r] = totff(a4.w);
            swi[q * 4 + 0][r] = totff(b4.x); swi[q * 4 + 1][r] = totff(b4.y);
            swi[q * 4 + 2][r] = totff(b4.z); swi[q * 4 + 3][r] = totff(b4.w);
        }
        __syncthreads();
#pragma unroll
        for (int k8 = 0; k8 < 16; k8 += 8) {
            unsigned int axr[2][4], axi[2][4], axin[2][4];
#pragma unroll
            for (int mi = 0; mi < 2; ++mi) {
                int tm = wm + mi * 16;
                axr[mi][0] = __float_as_uint(sar[k8 + tq][tm + g]);
                axr[mi][1] = __float_as_uint(sar[k8 + tq][tm + g + 8]);
                axr[mi][2] = __float_as_uint(sar[k8 + tq + 4][tm + g]);
                axr[mi][3] = __float_as_uint(sar[k8 + tq + 4][tm + g + 8]);
                axi[mi][0] = __float_as_uint(sai[k8 + tq][tm + g]);
                axi[mi][1] = __float_as_uint(sai[k8 + tq][tm + g + 8]);
                axi[mi][2] = __float_as_uint(sai[k8 + tq + 4][tm + g]);
                axi[mi][3] = __float_as_uint(sai[k8 + tq + 4][tm + g + 8]);
#pragma unroll
                for (int c = 0; c < 4; ++c) axin[mi][c] = axi[mi][c] ^ 0x80000000u;
            }
#pragma unroll
            for (int nj = 0; nj < 4; ++nj) {
                int tn = wn + nj * 8;
                unsigned int br0 = __float_as_uint(swr[k8 + tq][tn + g]);
                unsigned int br1 = __float_as_uint(swr[k8 + tq + 4][tn + g]);
                unsigned int bi0 = __float_as_uint(swi[k8 + tq][tn + g]);
                unsigned int bi1 = __float_as_uint(swi[k8 + tq + 4][tn + g]);
#pragma unroll
                for (int mi = 0; mi < 2; ++mi) {
                    mma8(Cre[mi][nj], axr[mi],  br0, br1);
                    mma8(Cre[mi][nj], axin[mi], bi0, bi1);
                    mma8(Cim[mi][nj], axr[mi],  bi0, bi1);
                    mma8(Cim[mi][nj], axi[mi],  br0, br1);
                }
            }
        }
        __syncthreads();
    }

    const int IM_OFF = BB * EE * TT;
#pragma unroll
    for (int nj = 0; nj < 4; ++nj) {
#pragma unroll
        for (int cc = 0; cc < 2; ++cc) {
            int n = n0 + wn + nj * 8 + tq * 2 + cc;
            float brr = g_b2r[n], bii = g_b2i[n];
            float* pr = out + ((b * EE + n) * TT);
#pragma unroll
            for (int mi = 0; mi < 2; ++mi) {
#pragma unroll
                for (int hh = 0; hh < 2; ++hh) {
                    int c = hh * 2 + cc;
                    int t = t0 + wm + mi * 16 + g + hh * 8;
                    pr[t]          = Cre[mi][nj][c] + brr;
                    pr[t + IM_OFF] = Cim[mi][nj][c] + bii;
                }
            }
        }
    }
}

// ---------------------------------------------------------------------------
extern "C" void kernel_launch(void* const* d_in, const int* in_sizes, int n_in,
                              void* d_out, int out_size)
{
    const float* xr  = (const float*)d_in[0];
    const float* xi  = (const float*)d_in[1];
    const float* wir = (const float*)d_in[2];
    const float* wii = (const float*)d_in[3];
    const float* bir = (const float*)d_in[4];
    const float* bii = (const float*)d_in[5];
    const float* wor = (const float*)d_in[6];
    const float* woi = (const float*)d_in[7];
    const float* bor = (const float*)d_in[8];
    const float* boi = (const float*)d_in[9];
    const float* wtr = (const float*)d_in[10];
    const float* wti = (const float*)d_in[11];
    const float* btr = (const float*)d_in[12];
    const float* bti = (const float*)d_in[13];

    combine_kernel<<<EE, EE>>>(wtr, wti, wor, woi, bor, boi, btr, bti);
    qkv_kernel<<<dim3((BB * TT) / 128, E3 / 64), 256>>>(xr, xi, wir, wii, bir, bii);
    attn_kernel<<<dim3(TT / 64, HH, BB), 128>>>();
    out_kernel<<<dim3((BB * TT) / 64, EE / 64), 128>>>((float*)d_out);
}